// round 7
// baseline (speedup 1.0000x reference)
#include <cuda_runtime.h>
#include <cuda_bf16.h>

// Problem: B=64, L=1024, D=1280
//   pool_len = lengths + 2
//   emb[b,d]  = mean over l < pool_len of prev[b,l,d]
//   x         = relu(emb @ dense_w + dense_b)        [64,1280]
//   out       = x @ cls_w + cls_b                    [64,1]
//
// Inputs: prev f32[64,1024,1280], lengths i32[64], dense_w f32[1280,1280],
//         dense_b f32[1280], cls_w f32[1280,1], cls_b f32[1]
// Output: f32[64,1]

#define Bq   64
#define Lq   1024
#define Dq   1280
#define D4   (Dq/4)          // 320 float4 per row
#define NSEG 16
#define SEGR (Lq/NSEG)       // 64 rows per segment

#define KS   4               // GEMM k-splits (each 320 k)
#define KCH  (Dq/KS)         // 320
#define KC   64              // k staged per chunk
#define JT   16              // j tile
#define NJ   (Dq/JT)         // 80

// scratch (allocation-free: __device__ globals)
__device__ float g_part [Bq * NSEG * Dq];   // pool partial sums (5.24 MB)
__device__ float g_emb  [Bq * Dq];          // pooled embedding  (0.33 MB)
__device__ float g_xpart[KS * Bq * Dq];     // GEMM k-partials   (1.31 MB)

// ---------------------------------------------------------------------------
// Kernel 1: ragged partial pool. grid(B, NSEG), 320 threads (one float4 col).
// MLP=8 rows in flight per thread.
// ---------------------------------------------------------------------------
__global__ void __launch_bounds__(D4) pool_kernel(
    const float* __restrict__ prev, const int* __restrict__ lengths)
{
    const int b   = blockIdx.x;
    const int seg = blockIdx.y;
    const int tid = threadIdx.x;

    const int pl = lengths[b] + 2;            // pool_len in [2, 1023]
    const int l0 = seg * SEGR;
    const int n  = min(SEGR, pl - l0);        // rows this block must sum

    float4 a0 = make_float4(0.f, 0.f, 0.f, 0.f);
    float4 a1 = a0, a2 = a0, a3 = a0;

    if (n > 0) {
        const float4* __restrict__ p =
            reinterpret_cast<const float4*>(prev) + ((size_t)b * Lq + l0) * D4 + tid;
        int l = 0;
        for (; l + 8 <= n; l += 8) {
            float4 v0 = p[(size_t)(l + 0) * D4];
            float4 v1 = p[(size_t)(l + 1) * D4];
            float4 v2 = p[(size_t)(l + 2) * D4];
            float4 v3 = p[(size_t)(l + 3) * D4];
            float4 v4 = p[(size_t)(l + 4) * D4];
            float4 v5 = p[(size_t)(l + 5) * D4];
            float4 v6 = p[(size_t)(l + 6) * D4];
            float4 v7 = p[(size_t)(l + 7) * D4];
            a0.x += v0.x; a0.y += v0.y; a0.z += v0.z; a0.w += v0.w;
            a1.x += v1.x; a1.y += v1.y; a1.z += v1.z; a1.w += v1.w;
            a2.x += v2.x; a2.y += v2.y; a2.z += v2.z; a2.w += v2.w;
            a3.x += v3.x; a3.y += v3.y; a3.z += v3.z; a3.w += v3.w;
            a0.x += v4.x; a0.y += v4.y; a0.z += v4.z; a0.w += v4.w;
            a1.x += v5.x; a1.y += v5.y; a1.z += v5.z; a1.w += v5.w;
            a2.x += v6.x; a2.y += v6.y; a2.z += v6.z; a2.w += v6.w;
            a3.x += v7.x; a3.y += v7.y; a3.z += v7.z; a3.w += v7.w;
        }
        for (; l < n; ++l) {
            float4 v = p[(size_t)l * D4];
            a0.x += v.x; a0.y += v.y; a0.z += v.z; a0.w += v.w;
        }
    }
    float4 s;
    s.x = (a0.x + a1.x) + (a2.x + a3.x);
    s.y = (a0.y + a1.y) + (a2.y + a3.y);
    s.z = (a0.z + a1.z) + (a2.z + a3.z);
    s.w = (a0.w + a1.w) + (a2.w + a3.w);

    reinterpret_cast<float4*>(g_part)[((size_t)b * NSEG + seg) * D4 + tid] = s;
}

// ---------------------------------------------------------------------------
// Kernel 2: reduce partials + divide by pool_len; also init out[b] = cls_b.
// grid(B, 5), block 64 (each block owns 64 float4 columns of one b)
// ---------------------------------------------------------------------------
__global__ void __launch_bounds__(64) reduce_kernel(
    const int* __restrict__ lengths,
    const float* __restrict__ cls_b,
    float* __restrict__ out)
{
    const int b   = blockIdx.x;
    const int tid = threadIdx.x;
    const int d4  = blockIdx.y * 64 + tid;          // 0..319
    const float4* gp = reinterpret_cast<const float4*>(g_part);

    float4 s = make_float4(0.f, 0.f, 0.f, 0.f);
#pragma unroll
    for (int seg = 0; seg < NSEG; ++seg) {
        float4 v = gp[((size_t)b * NSEG + seg) * D4 + d4];
        s.x += v.x; s.y += v.y; s.z += v.z; s.w += v.w;
    }
    const float inv = 1.0f / (float)(lengths[b] + 2);
    s.x *= inv; s.y *= inv; s.z *= inv; s.w *= inv;
    reinterpret_cast<float4*>(g_emb)[(size_t)b * D4 + d4] = s;

    // initialize output (runs before final_kernel's atomics, stream-ordered)
    if (blockIdx.x == 0 && blockIdx.y == 0)
        out[tid] = cls_b[0];
}

// ---------------------------------------------------------------------------
// Kernel 3: k-split GEMM partials, FMA-bound inner loop.
// grid(NJ=80, KS=4), block 128. Each thread: 2 b x 4 j register tile.
// ---------------------------------------------------------------------------
__global__ void __launch_bounds__(128) gemm_kernel(const float* __restrict__ W)
{
    __shared__ __align__(16) float sE[KC][66];  // emb^T chunk, padded pitch
    __shared__ __align__(16) float sW[KC][JT];  // W chunk

    const int tid = threadIdx.x;
    const int j0  = blockIdx.x * JT;
    const int k0  = blockIdx.y * KCH;
    const int bg  = tid >> 2;       // 0..31 -> rows 2bg, 2bg+1
    const int jg  = tid & 3;        // 0..3  -> cols 4jg..4jg+3

    float a00=0.f,a01=0.f,a02=0.f,a03=0.f;
    float a10=0.f,a11=0.f,a12=0.f,a13=0.f;

    for (int c = 0; c < KCH; c += KC) {
        __syncthreads();
        // stage emb^T: consecutive tid -> consecutive kk (coalesced gmem read)
        for (int i = tid; i < KC * Bq; i += 128) {
            int kk = i & (KC - 1);
            int b  = i >> 6;
            sE[kk][b] = g_emb[(size_t)b * Dq + k0 + c + kk];
        }
        // stage W tile
        for (int i = tid; i < KC * JT; i += 128) {
            int kk = i >> 4;
            int j  = i & (JT - 1);
            sW[kk][j] = W[(size_t)(k0 + c + kk) * Dq + j0 + j];
        }
        __syncthreads();

#pragma unroll 8
        for (int kk = 0; kk < KC; ++kk) {
            float2 e = *reinterpret_cast<const float2*>(&sE[kk][2 * bg]);
            float4 w = *reinterpret_cast<const float4*>(&sW[kk][4 * jg]);
            a00 += e.x * w.x; a01 += e.x * w.y; a02 += e.x * w.z; a03 += e.x * w.w;
            a10 += e.y * w.x; a11 += e.y * w.y; a12 += e.y * w.z; a13 += e.y * w.w;
        }
    }

    float* dst0 = &g_xpart[((size_t)blockIdx.y * Bq + 2 * bg) * Dq + j0 + 4 * jg];
    float* dst1 = dst0 + Dq;
    *reinterpret_cast<float4*>(dst0) = make_float4(a00, a01, a02, a03);
    *reinterpret_cast<float4*>(dst1) = make_float4(a10, a11, a12, a13);
}

// ---------------------------------------------------------------------------
// Kernel 4: reduce k-partials, +bias, relu, dot with cls_w, atomicAdd out.
// grid(B, 5), block 64 (each thread owns one float4 column)
// ---------------------------------------------------------------------------
__global__ void __launch_bounds__(64) final_kernel(
    const float* __restrict__ dense_b,
    const float* __restrict__ cls_w,
    float* __restrict__ out)
{
    const int b   = blockIdx.x;
    const int tid = threadIdx.x;
    const int d4  = blockIdx.y * 64 + tid;          // 0..319
    const float4* xp = reinterpret_cast<const float4*>(g_xpart);

    float4 s = reinterpret_cast<const float4*>(dense_b)[d4];
#pragma unroll
    for (int ks = 0; ks < KS; ++ks) {
        float4 v = xp[((size_t)ks * Bq + b) * D4 + d4];
        s.x += v.x; s.y += v.y; s.z += v.z; s.w += v.w;
    }
    s.x = fmaxf(s.x, 0.f); s.y = fmaxf(s.y, 0.f);
    s.z = fmaxf(s.z, 0.f); s.w = fmaxf(s.w, 0.f);

    float4 w = reinterpret_cast<const float4*>(cls_w)[d4];
    float part = s.x * w.x + s.y * w.y + s.z * w.z + s.w * w.w;

#pragma unroll
    for (int o = 16; o > 0; o >>= 1)
        part += __shfl_down_sync(0xffffffffu, part, o);
    if ((tid & 31) == 0)
        atomicAdd(&out[b], part);   // 2 atomics/block, 640 total over 64 addrs
}

// ---------------------------------------------------------------------------
extern "C" void kernel_launch(void* const* d_in, const int* in_sizes, int n_in,
                              void* d_out, int out_size)
{
    const float* prev    = (const float*)d_in[0];
    const int*   lengths = (const int*)  d_in[1];
    const float* dense_w = (const float*)d_in[2];
    const float* dense_b = (const float*)d_in[3];
    const float* cls_w   = (const float*)d_in[4];
    const float* cls_b   = (const float*)d_in[5];
    float*       out     = (float*)d_out;

    pool_kernel  <<<dim3(Bq, NSEG), D4>>>(prev, lengths);
    reduce_kernel<<<dim3(Bq, 5), 64>>>(lengths, cls_b, out);
    gemm_kernel  <<<dim3(NJ, KS), 128>>>(dense_w);
    final_kernel <<<dim3(Bq, 5), 64>>>(dense_b, cls_w, out);
}